// round 13
// baseline (speedup 1.0000x reference)
#include <cuda_runtime.h>
#include <cuda_fp16.h>
#include <stdint.h>

#define TOK 16384
#define CDIM 768
#define NCDIM 3072
#define DFFDIM 3072

// ---------------- device scratch (static; no allocs allowed) ----------------
__device__ __half g_xh[(size_t)TOK * NCDIM];      // x in fp16
__device__ float  g_invr[TOK];
__device__ __half g_phit[32 * NCDIM];             // phi^T padded [32][3072]
__device__ __half g_w1h[(size_t)CDIM * DFFDIM];   // W1 fp16, native [768][3072]
__device__ __half g_w2h[(size_t)DFFDIM * CDIM];   // W2 fp16, native [3072][768]
__device__ float  g_hpost[TOK * 4];
__device__ float  g_hres[TOK * 16];
__device__ __half g_xinh[(size_t)TOK * CDIM];     // pre-aggregated stream, fp16
__device__ __half g_hidh[(size_t)TOK * DFFDIM];   // gelu(x_in@W1+b1), fp16

// ---------------- kernel 1: rms sumsq + fp32->fp16 convert + phi pad ----------------
__global__ void sumsq_convert_kernel(const float* __restrict__ x,
                                     const float* __restrict__ phi) {
    int gid = blockIdx.x * blockDim.x + threadIdx.x;
    if (gid < 32 * NCDIM) {
        int j = gid / NCDIM, k = gid % NCDIM;
        g_phit[gid] = (j < 24) ? __float2half(phi[k * 24 + j]) : __float2half(0.0f);
    }
    int gw = gid >> 5;
    int lane = threadIdx.x & 31;
    if (gw >= TOK) return;
    const float4* row = (const float4*)(x + (size_t)gw * NCDIM);
    __half2* outrow = (__half2*)(g_xh + (size_t)gw * NCDIM);
    float ss = 0.f;
    #pragma unroll 4
    for (int i = lane; i < NCDIM / 4; i += 32) {
        float4 v = row[i];
        ss += v.x * v.x + v.y * v.y + v.z * v.z + v.w * v.w;
        outrow[2 * i]     = __floats2half2_rn(v.x, v.y);
        outrow[2 * i + 1] = __floats2half2_rn(v.z, v.w);
    }
    #pragma unroll
    for (int o = 16; o; o >>= 1) ss += __shfl_xor_sync(0xffffffffu, ss, o);
    if (lane == 0) g_invr[gw] = rsqrtf(ss / (float)NCDIM + 1e-6f);
}

// ---------------- cp.async helpers ----------------
#define CP_ASYNC16(dst, src) asm volatile("cp.async.cg.shared.global [%0], [%1], 16;\n" :: "r"(dst), "l"(src))
#define CP_COMMIT() asm volatile("cp.async.commit_group;\n" ::)
#define CP_WAIT(N_) asm volatile("cp.async.wait_group %0;\n" :: "n"(N_))

__device__ __forceinline__ float gelu_exact(float v) {
    return 0.5f * v * (1.0f + erff(v * 0.70710678118654752f));
}

// ============ kernel 2: fused mix GEMM + routing + x_in + weight convert ============
// blocks 0..255   : mix = x_h @ phi_t for 64 tokens -> sigmoid/sinkhorn -> x_in, all in-kernel.
// blocks 256..767 : fp32->fp16 weight conversion (1:1 coalesced), overlapped.
#define MIXBLKS 256
#define CONVBLKS 512

__global__ void __launch_bounds__(128, 2)
mix_routing_conv_kernel(const float* __restrict__ W1, const float* __restrict__ W2,
                        const float* __restrict__ b,  const float* __restrict__ apre,
                        const float* __restrict__ apost, const float* __restrict__ ares) {
    if (blockIdx.x >= MIXBLKS) {
        int i = (blockIdx.x - MIXBLKS) * 128 + threadIdx.x;
        const int stride = CONVBLKS * 128;
        const int WELEM4 = (CDIM * DFFDIM) / 4;
        for (int idx = i; idx < WELEM4; idx += stride) {
            float4 v = ((const float4*)W1)[idx];
            ((__half2*)g_w1h)[2 * idx]     = __floats2half2_rn(v.x, v.y);
            ((__half2*)g_w1h)[2 * idx + 1] = __floats2half2_rn(v.z, v.w);
            float4 w = ((const float4*)W2)[idx];
            ((__half2*)g_w2h)[2 * idx]     = __floats2half2_rn(w.x, w.y);
            ((__half2*)g_w2h)[2 * idx + 1] = __floats2half2_rn(w.z, w.w);
        }
        return;
    }

    constexpr int BM = 64, BK = 32, BN = 32;
    constexpr int THREADS = 128;
    constexpr int K = NCDIM, KT = K / BK;
    const __half* __restrict__ A  = g_xh;
    const __half* __restrict__ Bt = g_phit;

    __shared__ alignas(16) __half sA[2][BM * BK];
    __shared__ alignas(16) __half sB[2][BN * BK];
    __shared__ float smix[64][25];
    __shared__ float hpre_s[64][4];
    uint32_t sAb = (uint32_t)__cvta_generic_to_shared(&sA[0][0]);
    uint32_t sBb = (uint32_t)__cvta_generic_to_shared(&sB[0][0]);

    const int tid = threadIdx.x;
    const int mBase = blockIdx.x * BM;

    auto loadTiles = [&](int stg, int kt) {
        int k0 = kt * BK;
        #pragma unroll
        for (int it = 0; it < 2; it++) {
            int ch = tid + it * THREADS;
            int row = ch >> 2, k8 = ch & 3;
            const __half* g = A + (size_t)(mBase + row) * K + k0 + k8 * 8;
            uint32_t d = sAb + 2 * (stg * BM * BK + row * BK + ((k8 ^ ((row >> 1) & 3)) << 3));
            CP_ASYNC16(d, g);
        }
        {
            int ch = tid;
            int row = ch >> 2, k8 = ch & 3;
            const __half* g = Bt + (size_t)row * K + k0 + k8 * 8;
            uint32_t d = sBb + 2 * (stg * BN * BK + row * BK + ((k8 ^ ((row >> 1) & 3)) << 3));
            CP_ASYNC16(d, g);
        }
    };

    const int warp = tid >> 5, lane = tid & 31;
    float acc[4][4];
    #pragma unroll
    for (int j = 0; j < 4; j++)
        #pragma unroll
        for (int q = 0; q < 4; q++) acc[j][q] = 0.f;

    const int aRow = lane & 15, aKc = lane >> 4;
    const int bRow = lane & 7,  bKc = (lane >> 3) & 1;

    loadTiles(0, 0);
    CP_COMMIT();
    for (int kt = 0; kt < KT; kt++) {
        int cur = kt & 1;
        if (kt + 1 < KT) { loadTiles(cur ^ 1, kt + 1); CP_COMMIT(); CP_WAIT(1); }
        else             { CP_WAIT(0); }
        __syncthreads();
        #pragma unroll
        for (int ks = 0; ks < 2; ks++) {
            uint32_t a[4], bfr[4][2];
            {
                int row = warp * 16 + aRow;
                int k8 = ks * 2 + aKc;
                uint32_t ad = sAb + 2 * (cur * BM * BK + row * BK + ((k8 ^ ((row >> 1) & 3)) << 3));
                asm volatile("ldmatrix.sync.aligned.m8n8.x4.shared.b16 {%0,%1,%2,%3}, [%4];\n"
                             : "=r"(a[0]), "=r"(a[1]), "=r"(a[2]), "=r"(a[3]) : "r"(ad));
            }
            #pragma unroll
            for (int fn = 0; fn < 4; fn++) {
                int row = fn * 8 + bRow;
                int k8 = ks * 2 + bKc;
                uint32_t bd = sBb + 2 * (cur * BN * BK + row * BK + ((k8 ^ ((row >> 1) & 3)) << 3));
                asm volatile("ldmatrix.sync.aligned.m8n8.x2.shared.b16 {%0,%1}, [%2];\n"
                             : "=r"(bfr[fn][0]), "=r"(bfr[fn][1]) : "r"(bd));
            }
            #pragma unroll
            for (int fn = 0; fn < 4; fn++)
                asm volatile(
                    "mma.sync.aligned.m16n8k16.row.col.f32.f16.f16.f32 "
                    "{%0,%1,%2,%3}, {%4,%5,%6,%7}, {%8,%9}, {%0,%1,%2,%3};\n"
                    : "+f"(acc[fn][0]), "+f"(acc[fn][1]), "+f"(acc[fn][2]), "+f"(acc[fn][3])
                    : "r"(a[0]), "r"(a[1]), "r"(a[2]), "r"(a[3]),
                      "r"(bfr[fn][0]), "r"(bfr[fn][1]));
        }
        __syncthreads();
    }

    const int gq = lane >> 2, cq = lane & 3;
    {
        int rl0 = warp * 16 + gq, rl1 = rl0 + 8;
        #pragma unroll
        for (int fn = 0; fn < 3; fn++) {
            int c0 = fn * 8 + cq * 2;
            smix[rl0][c0] = acc[fn][0]; smix[rl0][c0 + 1] = acc[fn][1];
            smix[rl1][c0] = acc[fn][2]; smix[rl1][c0 + 1] = acc[fn][3];
        }
    }
    __syncthreads();

    // ---- routing (one thread per token), h_pre kept in smem ----
    if (tid < 64) {
        int t = mBase + tid;
        float invr = g_invr[t];
        float m[24];
        #pragma unroll
        for (int i = 0; i < 24; i++) m[i] = smix[tid][i] * invr;
        float ap = apre[0], apo = apost[0], ar = ares[0];
        #pragma unroll
        for (int n = 0; n < 4; n++)
            hpre_s[tid][n] = __fdividef(1.0f, 1.0f + __expf(-(m[n] * ap + b[n])));
        #pragma unroll
        for (int n = 0; n < 4; n++)
            g_hpost[t * 4 + n] = __fdividef(2.0f, 1.0f + __expf(-(m[4 + n] * apo + b[4 + n])));
        float r[16];
        #pragma unroll
        for (int i = 0; i < 16; i++) r[i] = m[8 + i] * ar + b[8 + i];
        #pragma unroll
        for (int row = 0; row < 4; row++) {
            float mx = r[row * 4];
            #pragma unroll
            for (int j = 1; j < 4; j++) mx = fmaxf(mx, r[row * 4 + j]);
            #pragma unroll
            for (int j = 0; j < 4; j++) r[row * 4 + j] = __expf(r[row * 4 + j] - mx);
        }
        for (int it = 0; it < 20; it++) {
            #pragma unroll
            for (int row = 0; row < 4; row++) {
                float inv = __fdividef(1.0f, r[row * 4] + r[row * 4 + 1] + r[row * 4 + 2] + r[row * 4 + 3] + 1e-6f);
                #pragma unroll
                for (int j = 0; j < 4; j++) r[row * 4 + j] *= inv;
            }
            #pragma unroll
            for (int col = 0; col < 4; col++) {
                float inv = __fdividef(1.0f, r[col] + r[4 + col] + r[8 + col] + r[12 + col] + 1e-6f);
                #pragma unroll
                for (int row = 0; row < 4; row++) r[row * 4 + col] *= inv;
            }
        }
        #pragma unroll
        for (int i = 0; i < 16; i++) g_hres[t * 16 + i] = r[i];
    }
    __syncthreads();

    // ---- fused x_in: x_in[t][c] = sum_n hpre[n] * x[t][n][c]  (rows warm in L2) ----
    {
        const __half2* xh2 = (const __half2*)g_xh;
        #pragma unroll 2
        for (int i = tid; i < 64 * 384; i += THREADS) {
            int tt = i / 384, c2 = i % 384;
            int t = mBase + tt;
            float h0 = hpre_s[tt][0], h1 = hpre_s[tt][1], h2 = hpre_s[tt][2], h3 = hpre_s[tt][3];
            size_t base = (size_t)t * 1536 + c2;
            float2 v0 = __half22float2(xh2[base]);
            float2 v1 = __half22float2(xh2[base + 384]);
            float2 v2 = __half22float2(xh2[base + 768]);
            float2 v3 = __half22float2(xh2[base + 1152]);
            float ax = h0 * v0.x + h1 * v1.x + h2 * v2.x + h3 * v3.x;
            float ay = h0 * v0.y + h1 * v1.y + h2 * v2.y + h3 * v3.y;
            ((__half2*)g_xinh)[(size_t)t * 384 + c2] = __floats2half2_rn(ax, ay);
        }
    }
}

// ================= big GEMM: BM=128, BN=128, BK=64, 3-stage, trans-B (R11-proven) =================
#define HP_STAGES 3
#define HP_STG_BYTES (256 * 64 * 2)   // A(128x64) 16KB + B(64x128) 16KB per stage
#define HP_THREADS 128

template <int KDIM, int EPI>
__global__ void __launch_bounds__(HP_THREADS, 2)
gemm_hp(const float* __restrict__ bias, float* __restrict__ out) {
    constexpr int BM = 128, BK = 64;
    constexpr int KT = KDIM / BK;
    constexpr int WN = (EPI == 1) ? DFFDIM : CDIM;   // weight row length (n-dim)

    const __half* __restrict__ A  = (EPI == 1) ? g_xinh : g_hidh;
    const __half* __restrict__ Bw = (EPI == 1) ? g_w1h  : g_w2h;

    extern __shared__ char smem_raw[];
    uint32_t sAb = (uint32_t)__cvta_generic_to_shared(smem_raw);

    const int tid = threadIdx.x, warp = tid >> 5, lane = tid & 31;
    const int mBase = blockIdx.y * BM;
    const int nBase = blockIdx.x * 128;
    const int wm = warp >> 1, wn = warp & 1;     // 2x2 warps, each 64x64

    auto loadTiles = [&](int stg, int kt) {
        int k0 = kt * BK;
        uint32_t sb = sAb + stg * HP_STG_BYTES;
        #pragma unroll
        for (int it = 0; it < 8; it++) {          // A: 128 rows x 8 chunks (128B rows)
            int ch = tid + it * HP_THREADS;
            int row = ch >> 3, c = ch & 7;
            const __half* g = A + (size_t)(mBase + row) * KDIM + k0 + c * 8;
            CP_ASYNC16(sb + row * 128 + ((c ^ (row & 7)) << 4), g);
        }
        #pragma unroll
        for (int it = 0; it < 8; it++) {          // B: 64 k-rows x 16 chunks (256B rows)
            int ch = tid + it * HP_THREADS;
            int row = ch >> 4, c = ch & 15;
            const __half* g = Bw + (size_t)(k0 + row) * WN + nBase + c * 8;
            CP_ASYNC16(sb + 16384 + row * 256 + ((c ^ (row & 7)) << 4), g);
        }
    };

    const int aRow = lane & 15, aKc = lane >> 4;

    float acc[4][8][4];
    #pragma unroll
    for (int i = 0; i < 4; i++)
        #pragma unroll
        for (int j = 0; j < 8; j++)
            #pragma unroll
            for (int q = 0; q < 4; q++) acc[i][j][q] = 0.f;

    loadTiles(0, 0); CP_COMMIT();
    loadTiles(1, 1); CP_COMMIT();

    for (int kt = 0; kt < KT; kt++) {
        int cur = kt % 3;
        if (kt + 2 < KT) { loadTiles((kt + 2) % 3, kt + 2); CP_COMMIT(); CP_WAIT(2); }
        else             { CP_WAIT(0); }
        __syncthreads();

        uint32_t sb = sAb + cur * HP_STG_BYTES;
        #pragma unroll
        for (int ks = 0; ks < 4; ks++) {
            uint32_t a[4][4], b[8][2];
            #pragma unroll
            for (int fm = 0; fm < 4; fm++) {
                int row = wm * 64 + fm * 16 + aRow;
                int c = ks * 2 + aKc;
                uint32_t ad = sb + row * 128 + ((c ^ (row & 7)) << 4);
                asm volatile("ldmatrix.sync.aligned.m8n8.x4.shared.b16 {%0,%1,%2,%3}, [%4];\n"
                             : "=r"(a[fm][0]), "=r"(a[fm][1]), "=r"(a[fm][2]), "=r"(a[fm][3])
                             : "r"(ad));
            }
            {
                int krow = ks * 16 + (lane & 15);
                #pragma unroll
                for (int fn = 0; fn < 8; fn++) {
                    int chunkN = (wn * 64 + fn * 8) >> 3;        // 16B chunk along n
                    uint32_t bd = sb + 16384 + krow * 256 + ((chunkN ^ (krow & 7)) << 4);
                    asm volatile("ldmatrix.sync.aligned.m8n8.x2.trans.shared.b16 {%0,%1}, [%2];\n"
                                 : "=r"(b[fn][0]), "=r"(b[fn][1])
                                 : "r"(bd));
                }
            }
            #pragma unroll
            for (int fm = 0; fm < 4; fm++)
                #pragma unroll
                for (int fn = 0; fn < 8; fn++)
                    asm volatile(
                        "mma.sync.aligned.m16n8k16.row.col.f32.f16.f16.f32 "
                        "{%0,%1,%2,%3}, {%4,%5,%6,%7}, {%8,%9}, {%0,%1,%2,%3};\n"
                        : "+f"(acc[fm][fn][0]), "+f"(acc[fm][fn][1]),
                          "+f"(acc[fm][fn][2]), "+f"(acc[fm][fn][3])
                        : "r"(a[fm][0]), "r"(a[fm][1]), "r"(a[fm][2]), "r"(a[fm][3]),
                          "r"(b[fn][0]), "r"(b[fn][1]));
        }
        __syncthreads();
    }

    // ---------------- epilogues (R11-verbatim) ----------------
    const int gq = lane >> 2, cq = lane & 3;
    if constexpr (EPI == 1) {
        #pragma unroll
        for (int fm = 0; fm < 4; fm++)
            #pragma unroll
            for (int fn = 0; fn < 8; fn++) {
                int r0 = mBase + wm * 64 + fm * 16 + gq;
                int c0 = nBase + wn * 64 + fn * 8 + cq * 2;
                float bz0 = bias[c0], bz1 = bias[c0 + 1];
                float v0 = gelu_exact(acc[fm][fn][0] + bz0);
                float v1 = gelu_exact(acc[fm][fn][1] + bz1);
                float v2 = gelu_exact(acc[fm][fn][2] + bz0);
                float v3 = gelu_exact(acc[fm][fn][3] + bz1);
                __half2* o = (__half2*)g_hidh;
                o[((size_t)r0 * DFFDIM + c0) >> 1]       = __floats2half2_rn(v0, v1);
                o[((size_t)(r0 + 8) * DFFDIM + c0) >> 1] = __floats2half2_rn(v2, v3);
            }
    } else {
        #pragma unroll
        for (int fm = 0; fm < 4; fm++) {
            int r0 = mBase + wm * 64 + fm * 16 + gq;
            int r1 = r0 + 8;
            float hp0[4], hp1[4], hr0[16], hr1[16];
            #pragma unroll
            for (int n = 0; n < 4; n++) { hp0[n] = g_hpost[r0 * 4 + n]; hp1[n] = g_hpost[r1 * 4 + n]; }
            #pragma unroll
            for (int i = 0; i < 16; i++) { hr0[i] = g_hres[r0 * 16 + i]; hr1[i] = g_hres[r1 * 16 + i]; }
            #pragma unroll
            for (int fn = 0; fn < 8; fn++) {
                int c0 = nBase + wn * 64 + fn * 8 + cq * 2;
                float bz0 = bias[c0], bz1 = bias[c0 + 1];
                float f0x = acc[fm][fn][0] + bz0, f0y = acc[fm][fn][1] + bz1;
                float f1x = acc[fm][fn][2] + bz0, f1y = acc[fm][fn][3] + bz1;
                float2 x0[4], x1[4];
                #pragma unroll
                for (int j = 0; j < 4; j++) {
                    x0[j] = __half22float2(*(const __half2*)(g_xh + (size_t)r0 * NCDIM + j * CDIM + c0));
                    x1[j] = __half22float2(*(const __half2*)(g_xh + (size_t)r1 * NCDIM + j * CDIM + c0));
                }
                #pragma unroll
                for (int n = 0; n < 4; n++) {
                    float ox = hp0[n] * f0x, oy = hp0[n] * f0y;
                    #pragma unroll
                    for (int j = 0; j < 4; j++) {
                        ox += hr0[n * 4 + j] * x0[j].x;
                        oy += hr0[n * 4 + j] * x0[j].y;
                    }
                    *(float2*)(out + ((size_t)r0 * 4 + n) * CDIM + c0) = make_float2(ox, oy);
                }
                #pragma unroll
                for (int n = 0; n < 4; n++) {
                    float ox = hp1[n] * f1x, oy = hp1[n] * f1y;
                    #pragma unroll
                    for (int j = 0; j < 4; j++) {
                        ox += hr1[n * 4 + j] * x1[j].x;
                        oy += hr1[n * 4 + j] * x1[j].y;
                    }
                    *(float2*)(out + ((size_t)r1 * 4 + n) * CDIM + c0) = make_float2(ox, oy);
                }
            }
        }
    }
}

// ---------------- launch ----------------
extern "C" void kernel_launch(void* const* d_in, const int* in_sizes, int n_in,
                              void* d_out, int out_size) {
    const float* x     = (const float*)d_in[0];
    const float* phi   = (const float*)d_in[1];
    const float* b     = (const float*)d_in[2];
    const float* apre  = (const float*)d_in[3];
    const float* apost = (const float*)d_in[4];
    const float* ares  = (const float*)d_in[5];
    const float* W1    = (const float*)d_in[6];
    const float* b1    = (const float*)d_in[7];
    const float* W2    = (const float*)d_in[8];
    const float* b2    = (const float*)d_in[9];
    float* out = (float*)d_out;

    const int dyn_smem = HP_STAGES * HP_STG_BYTES;   // 96 KB
    cudaFuncSetAttribute(gemm_hp<CDIM, 1>,  cudaFuncAttributeMaxDynamicSharedMemorySize, dyn_smem);
    cudaFuncSetAttribute(gemm_hp<NCDIM, 2>, cudaFuncAttributeMaxDynamicSharedMemorySize, dyn_smem);

    sumsq_convert_kernel<<<TOK / 8, 256>>>(x, phi);
    mix_routing_conv_kernel<<<MIXBLKS + CONVBLKS, 128>>>(W1, W2, b, apre, apost, ares);
    gemm_hp<CDIM, 1><<<dim3(DFFDIM / 128, TOK / 128), HP_THREADS, dyn_smem>>>(b1, nullptr);
    gemm_hp<NCDIM, 2><<<dim3(CDIM / 128, TOK / 128), HP_THREADS, dyn_smem>>>(b2, out);
}

// round 14
// speedup vs baseline: 1.1207x; 1.1207x over previous
#include <cuda_runtime.h>
#include <cuda_fp16.h>
#include <stdint.h>

#define TOK 16384
#define CDIM 768
#define NCDIM 3072
#define DFFDIM 3072

// ---------------- device scratch (static; no allocs allowed) ----------------
__device__ __half g_xh[(size_t)TOK * NCDIM];      // x in fp16
__device__ float  g_invr[TOK];
__device__ __half g_phit[32 * NCDIM];             // phi^T padded [32][3072]
__device__ __half g_w1h[(size_t)CDIM * DFFDIM];   // W1 fp16, native [768][3072]
__device__ __half g_w2h[(size_t)DFFDIM * CDIM];   // W2 fp16, native [3072][768]
__device__ float  g_hpre[TOK * 4];
__device__ float  g_hpost[TOK * 4];
__device__ float  g_hres[TOK * 16];
__device__ __half g_xinh[(size_t)TOK * CDIM];     // pre-aggregated stream, fp16
__device__ __half g_hidh[(size_t)TOK * DFFDIM];   // gelu(x_in@W1+b1), fp16

// ---- kernel 1: rms sumsq + fp32->fp16 convert + phi pad + weight convert (indep blocks) ----
#define SSBLKS 2048
#define WCBLKS 256

__global__ void sumsq_convert_kernel(const float* __restrict__ x,
                                     const float* __restrict__ phi,
                                     const float* __restrict__ W1,
                                     const float* __restrict__ W2) {
    if (blockIdx.x >= SSBLKS) {
        // ---- weight conversion path (independent of x; proven 1:1 coalesced loop) ----
        int i = (blockIdx.x - SSBLKS) * 256 + threadIdx.x;
        const int stride = WCBLKS * 256;
        const int WELEM4 = (CDIM * DFFDIM) / 4;
        for (int idx = i; idx < WELEM4; idx += stride) {
            float4 v = ((const float4*)W1)[idx];
            ((__half2*)g_w1h)[2 * idx]     = __floats2half2_rn(v.x, v.y);
            ((__half2*)g_w1h)[2 * idx + 1] = __floats2half2_rn(v.z, v.w);
            float4 w = ((const float4*)W2)[idx];
            ((__half2*)g_w2h)[2 * idx]     = __floats2half2_rn(w.x, w.y);
            ((__half2*)g_w2h)[2 * idx + 1] = __floats2half2_rn(w.z, w.w);
        }
        return;
    }
    int gid = blockIdx.x * blockDim.x + threadIdx.x;
    if (gid < 32 * NCDIM) {
        int j = gid / NCDIM, k = gid % NCDIM;
        g_phit[gid] = (j < 24) ? __float2half(phi[k * 24 + j]) : __float2half(0.0f);
    }
    int gw = gid >> 5;
    int lane = threadIdx.x & 31;
    if (gw >= TOK) return;
    const float4* row = (const float4*)(x + (size_t)gw * NCDIM);
    __half2* outrow = (__half2*)(g_xh + (size_t)gw * NCDIM);
    float ss = 0.f;
    #pragma unroll 4
    for (int i = lane; i < NCDIM / 4; i += 32) {
        float4 v = row[i];
        ss += v.x * v.x + v.y * v.y + v.z * v.z + v.w * v.w;
        outrow[2 * i]     = __floats2half2_rn(v.x, v.y);
        outrow[2 * i + 1] = __floats2half2_rn(v.z, v.w);
    }
    #pragma unroll
    for (int o = 16; o; o >>= 1) ss += __shfl_xor_sync(0xffffffffu, ss, o);
    if (lane == 0) g_invr[gw] = rsqrtf(ss / (float)NCDIM + 1e-6f);
}

// ---------------- cp.async helpers ----------------
#define CP_ASYNC16(dst, src) asm volatile("cp.async.cg.shared.global [%0], [%1], 16;\n" :: "r"(dst), "l"(src))
#define CP_COMMIT() asm volatile("cp.async.commit_group;\n" ::)
#define CP_WAIT(N_) asm volatile("cp.async.wait_group %0;\n" :: "n"(N_))

__device__ __forceinline__ float gelu_exact(float v) {
    return 0.5f * v * (1.0f + erff(v * 0.70710678118654752f));
}

// ============ kernel 2: fused mix GEMM (BM=64) + routing epilogue ============
#define MIXBLKS 256

__global__ void __launch_bounds__(128, 2)
mix_routing_kernel(const float* __restrict__ b,  const float* __restrict__ apre,
                   const float* __restrict__ apost, const float* __restrict__ ares) {
    constexpr int BM = 64, BK = 32, BN = 32;
    constexpr int THREADS = 128;
    constexpr int K = NCDIM, KT = K / BK;
    const __half* __restrict__ A  = g_xh;
    const __half* __restrict__ Bt = g_phit;

    __shared__ alignas(16) __half sA[2][BM * BK];
    __shared__ alignas(16) __half sB[2][BN * BK];
    __shared__ float smix[64][25];
    uint32_t sAb = (uint32_t)__cvta_generic_to_shared(&sA[0][0]);
    uint32_t sBb = (uint32_t)__cvta_generic_to_shared(&sB[0][0]);

    const int tid = threadIdx.x;
    const int mBase = blockIdx.x * BM;

    auto loadTiles = [&](int stg, int kt) {
        int k0 = kt * BK;
        #pragma unroll
        for (int it = 0; it < 2; it++) {
            int ch = tid + it * THREADS;
            int row = ch >> 2, k8 = ch & 3;
            const __half* g = A + (size_t)(mBase + row) * K + k0 + k8 * 8;
            uint32_t d = sAb + 2 * (stg * BM * BK + row * BK + ((k8 ^ ((row >> 1) & 3)) << 3));
            CP_ASYNC16(d, g);
        }
        {
            int ch = tid;
            int row = ch >> 2, k8 = ch & 3;
            const __half* g = Bt + (size_t)row * K + k0 + k8 * 8;
            uint32_t d = sBb + 2 * (stg * BN * BK + row * BK + ((k8 ^ ((row >> 1) & 3)) << 3));
            CP_ASYNC16(d, g);
        }
    };

    const int warp = tid >> 5, lane = tid & 31;
    float acc[4][4];
    #pragma unroll
    for (int j = 0; j < 4; j++)
        #pragma unroll
        for (int q = 0; q < 4; q++) acc[j][q] = 0.f;

    const int aRow = lane & 15, aKc = lane >> 4;
    const int bRow = lane & 7,  bKc = (lane >> 3) & 1;

    loadTiles(0, 0);
    CP_COMMIT();
    for (int kt = 0; kt < KT; kt++) {
        int cur = kt & 1;
        if (kt + 1 < KT) { loadTiles(cur ^ 1, kt + 1); CP_COMMIT(); CP_WAIT(1); }
        else             { CP_WAIT(0); }
        __syncthreads();
        #pragma unroll
        for (int ks = 0; ks < 2; ks++) {
            uint32_t a[4], bfr[4][2];
            {
                int row = warp * 16 + aRow;
                int k8 = ks * 2 + aKc;
                uint32_t ad = sAb + 2 * (cur * BM * BK + row * BK + ((k8 ^ ((row >> 1) & 3)) << 3));
                asm volatile("ldmatrix.sync.aligned.m8n8.x4.shared.b16 {%0,%1,%2,%3}, [%4];\n"
                             : "=r"(a[0]), "=r"(a[1]), "=r"(a[2]), "=r"(a[3]) : "r"(ad));
            }
            #pragma unroll
            for (int fn = 0; fn < 4; fn++) {
                int row = fn * 8 + bRow;
                int k8 = ks * 2 + bKc;
                uint32_t bd = sBb + 2 * (cur * BN * BK + row * BK + ((k8 ^ ((row >> 1) & 3)) << 3));
                asm volatile("ldmatrix.sync.aligned.m8n8.x2.shared.b16 {%0,%1}, [%2];\n"
                             : "=r"(bfr[fn][0]), "=r"(bfr[fn][1]) : "r"(bd));
            }
            #pragma unroll
            for (int fn = 0; fn < 4; fn++)
                asm volatile(
                    "mma.sync.aligned.m16n8k16.row.col.f32.f16.f16.f32 "
                    "{%0,%1,%2,%3}, {%4,%5,%6,%7}, {%8,%9}, {%0,%1,%2,%3};\n"
                    : "+f"(acc[fn][0]), "+f"(acc[fn][1]), "+f"(acc[fn][2]), "+f"(acc[fn][3])
                    : "r"(a[0]), "r"(a[1]), "r"(a[2]), "r"(a[3]),
                      "r"(bfr[fn][0]), "r"(bfr[fn][1]));
        }
        __syncthreads();
    }

    const int gq = lane >> 2, cq = lane & 3;
    {
        int rl0 = warp * 16 + gq, rl1 = rl0 + 8;
        #pragma unroll
        for (int fn = 0; fn < 3; fn++) {
            int c0 = fn * 8 + cq * 2;
            smix[rl0][c0] = acc[fn][0]; smix[rl0][c0 + 1] = acc[fn][1];
            smix[rl1][c0] = acc[fn][2]; smix[rl1][c0 + 1] = acc[fn][3];
        }
    }
    __syncthreads();

    if (tid < 64) {
        int t = mBase + tid;
        float invr = g_invr[t];
        float m[24];
        #pragma unroll
        for (int i = 0; i < 24; i++) m[i] = smix[tid][i] * invr;
        float ap = apre[0], apo = apost[0], ar = ares[0];
        #pragma unroll
        for (int n = 0; n < 4; n++)
            g_hpre[t * 4 + n] = __fdividef(1.0f, 1.0f + __expf(-(m[n] * ap + b[n])));
        #pragma unroll
        for (int n = 0; n < 4; n++)
            g_hpost[t * 4 + n] = __fdividef(2.0f, 1.0f + __expf(-(m[4 + n] * apo + b[4 + n])));
        float r[16];
        #pragma unroll
        for (int i = 0; i < 16; i++) r[i] = m[8 + i] * ar + b[8 + i];
        #pragma unroll
        for (int row = 0; row < 4; row++) {
            float mx = r[row * 4];
            #pragma unroll
            for (int j = 1; j < 4; j++) mx = fmaxf(mx, r[row * 4 + j]);
            #pragma unroll
            for (int j = 0; j < 4; j++) r[row * 4 + j] = __expf(r[row * 4 + j] - mx);
        }
        for (int it = 0; it < 20; it++) {
            #pragma unroll
            for (int row = 0; row < 4; row++) {
                float inv = __fdividef(1.0f, r[row * 4] + r[row * 4 + 1] + r[row * 4 + 2] + r[row * 4 + 3] + 1e-6f);
                #pragma unroll
                for (int j = 0; j < 4; j++) r[row * 4 + j] *= inv;
            }
            #pragma unroll
            for (int col = 0; col < 4; col++) {
                float inv = __fdividef(1.0f, r[col] + r[4 + col] + r[8 + col] + r[12 + col] + 1e-6f);
                #pragma unroll
                for (int row = 0; row < 4; row++) r[row * 4 + col] *= inv;
            }
        }
        #pragma unroll
        for (int i = 0; i < 16; i++) g_hres[t * 16 + i] = r[i];
    }
}

// ---------------- kernel 3: x_in = sum_n h_pre[n] * x[n,:] (R11-proven) ----------------
__global__ void xin_kernel() {
    int idx = blockIdx.x * blockDim.x + threadIdx.x;
    if (idx >= TOK * 384) return;
    int t = idx / 384, c2 = idx % 384;
    const __half2* xh2 = (const __half2*)g_xh;
    float ax = 0.f, ay = 0.f;
    #pragma unroll
    for (int n = 0; n < 4; n++) {
        float2 v = __half22float2(xh2[(size_t)t * 1536 + n * 384 + c2]);
        float h = g_hpre[t * 4 + n];
        ax += h * v.x; ay += h * v.y;
    }
    ((__half2*)g_xinh)[(size_t)t * 384 + c2] = __floats2half2_rn(ax, ay);
}

// ================= big GEMM: BM=128, BN=128, BK=64, 3-stage, trans-B (R11-proven) =================
#define HP_STAGES 3
#define HP_STG_BYTES (256 * 64 * 2)   // A(128x64) 16KB + B(64x128) 16KB per stage
#define HP_THREADS 128

template <int KDIM, int EPI>
__global__ void __launch_bounds__(HP_THREADS, 2)
gemm_hp(const float* __restrict__ bias, float* __restrict__ out) {
    constexpr int BM = 128, BK = 64;
    constexpr int KT = KDIM / BK;
    constexpr int WN = (EPI == 1) ? DFFDIM : CDIM;   // weight row length (n-dim)

    const __half* __restrict__ A  = (EPI == 1) ? g_xinh : g_hidh;
    const __half* __restrict__ Bw = (EPI == 1) ? g_w1h  : g_w2h;

    extern __shared__ char smem_raw[];
    uint32_t sAb = (uint32_t)__cvta_generic_to_shared(smem_raw);

    const int tid = threadIdx.x, warp = tid >> 5, lane = tid & 31;
    const int mBase = blockIdx.y * BM;
    const int nBase = blockIdx.x * 128;
    const int wm = warp >> 1, wn = warp & 1;     // 2x2 warps, each 64x64

    auto loadTiles = [&](int stg, int kt) {
        int k0 = kt * BK;
        uint32_t sb = sAb + stg * HP_STG_BYTES;
        #pragma unroll
        for (int it = 0; it < 8; it++) {          // A: 128 rows x 8 chunks (128B rows)
            int ch = tid + it * HP_THREADS;
            int row = ch >> 3, c = ch & 7;
            const __half* g = A + (size_t)(mBase + row) * KDIM + k0 + c * 8;
            CP_ASYNC16(sb + row * 128 + ((c ^ (row & 7)) << 4), g);
        }
        #pragma unroll
        for (int it = 0; it < 8; it++) {          // B: 64 k-rows x 16 chunks (256B rows)
            int ch = tid + it * HP_THREADS;
            int row = ch >> 4, c = ch & 15;
            const __half* g = Bw + (size_t)(k0 + row) * WN + nBase + c * 8;
            CP_ASYNC16(sb + 16384 + row * 256 + ((c ^ (row & 7)) << 4), g);
        }
    };

    const int aRow = lane & 15, aKc = lane >> 4;

    float acc[4][8][4];
    #pragma unroll
    for (int i = 0; i < 4; i++)
        #pragma unroll
        for (int j = 0; j < 8; j++)
            #pragma unroll
            for (int q = 0; q < 4; q++) acc[i][j][q] = 0.f;

    loadTiles(0, 0); CP_COMMIT();
    loadTiles(1, 1); CP_COMMIT();

    for (int kt = 0; kt < KT; kt++) {
        int cur = kt % 3;
        if (kt + 2 < KT) { loadTiles((kt + 2) % 3, kt + 2); CP_COMMIT(); CP_WAIT(2); }
        else             { CP_WAIT(0); }
        __syncthreads();

        uint32_t sb = sAb + cur * HP_STG_BYTES;
        #pragma unroll
        for (int ks = 0; ks < 4; ks++) {
            uint32_t a[4][4], b[8][2];
            #pragma unroll
            for (int fm = 0; fm < 4; fm++) {
                int row = wm * 64 + fm * 16 + aRow;
                int c = ks * 2 + aKc;
                uint32_t ad = sb + row * 128 + ((c ^ (row & 7)) << 4);
                asm volatile("ldmatrix.sync.aligned.m8n8.x4.shared.b16 {%0,%1,%2,%3}, [%4];\n"
                             : "=r"(a[fm][0]), "=r"(a[fm][1]), "=r"(a[fm][2]), "=r"(a[fm][3])
                             : "r"(ad));
            }
            {
                int krow = ks * 16 + (lane & 15);
                #pragma unroll
                for (int fn = 0; fn < 8; fn++) {
                    int chunkN = (wn * 64 + fn * 8) >> 3;        // 16B chunk along n
                    uint32_t bd = sb + 16384 + krow * 256 + ((chunkN ^ (krow & 7)) << 4);
                    asm volatile("ldmatrix.sync.aligned.m8n8.x2.trans.shared.b16 {%0,%1}, [%2];\n"
                                 : "=r"(b[fn][0]), "=r"(b[fn][1])
                                 : "r"(bd));
                }
            }
            #pragma unroll
            for (int fm = 0; fm < 4; fm++)
                #pragma unroll
                for (int fn = 0; fn < 8; fn++)
                    asm volatile(
                        "mma.sync.aligned.m16n8k16.row.col.f32.f16.f16.f32 "
                        "{%0,%1,%2,%3}, {%4,%5,%6,%7}, {%8,%9}, {%0,%1,%2,%3};\n"
                        : "+f"(acc[fm][fn][0]), "+f"(acc[fm][fn][1]),
                          "+f"(acc[fm][fn][2]), "+f"(acc[fm][fn][3])
                        : "r"(a[fm][0]), "r"(a[fm][1]), "r"(a[fm][2]), "r"(a[fm][3]),
                          "r"(b[fn][0]), "r"(b[fn][1]));
        }
        __syncthreads();
    }

    // ---------------- epilogues (R11-verbatim) ----------------
    const int gq = lane >> 2, cq = lane & 3;
    if constexpr (EPI == 1) {
        #pragma unroll
        for (int fm = 0; fm < 4; fm++)
            #pragma unroll
            for (int fn = 0; fn < 8; fn++) {
                int r0 = mBase + wm * 64 + fm * 16 + gq;
                int c0 = nBase + wn * 64 + fn * 8 + cq * 2;
                float bz0 = bias[c0], bz1 = bias[c0 + 1];
                float v0 = gelu_exact(acc[fm][fn][0] + bz0);
                float v1 = gelu_exact(acc[fm][fn][1] + bz1);
                float v2 = gelu_exact(acc[fm][fn][2] + bz0);
                float v3 = gelu_exact(acc[fm][fn][3] + bz1);
                __half2* o = (__half2*)g_hidh;
                o[((size_t)r0 * DFFDIM + c0) >> 1]       = __floats2half2_rn(v0, v1);
                o[((size_t)(r0 + 8) * DFFDIM + c0) >> 1] = __floats2half2_rn(v2, v3);
            }
    } else {
        #pragma unroll
        for (int fm = 0; fm < 4; fm++) {
            int r0 = mBase + wm * 64 + fm * 16 + gq;
            int r1 = r0 + 8;
            float hp0[4], hp1[4], hr0[16], hr1[16];
            #pragma unroll
            for (int n = 0; n < 4; n++) { hp0[n] = g_hpost[r0 * 4 + n]; hp1[n] = g_hpost[r1 * 4 + n]; }
            #pragma unroll
            for (int i = 0; i < 16; i++) { hr0[i] = g_hres[r0 * 16 + i]; hr1[i] = g_hres[r1 * 16 + i]; }
            #pragma unroll
            for (int fn = 0; fn < 8; fn++) {
                int c0 = nBase + wn * 64 + fn * 8 + cq * 2;
                float bz0 = bias[c0], bz1 = bias[c0 + 1];
                float f0x = acc[fm][fn][0] + bz0, f0y = acc[fm][fn][1] + bz1;
                float f1x = acc[fm][fn][2] + bz0, f1y = acc[fm][fn][3] + bz1;
                float2 x0[4], x1[4];
                #pragma unroll
                for (int j = 0; j < 4; j++) {
                    x0[j] = __half22float2(*(const __half2*)(g_xh + (size_t)r0 * NCDIM + j * CDIM + c0));
                    x1[j] = __half22float2(*(const __half2*)(g_xh + (size_t)r1 * NCDIM + j * CDIM + c0));
                }
                #pragma unroll
                for (int n = 0; n < 4; n++) {
                    float ox = hp0[n] * f0x, oy = hp0[n] * f0y;
                    #pragma unroll
                    for (int j = 0; j < 4; j++) {
                        ox += hr0[n * 4 + j] * x0[j].x;
                        oy += hr0[n * 4 + j] * x0[j].y;
                    }
                    *(float2*)(out + ((size_t)r0 * 4 + n) * CDIM + c0) = make_float2(ox, oy);
                }
                #pragma unroll
                for (int n = 0; n < 4; n++) {
                    float ox = hp1[n] * f1x, oy = hp1[n] * f1y;
                    #pragma unroll
                    for (int j = 0; j < 4; j++) {
                        ox += hr1[n * 4 + j] * x1[j].x;
                        oy += hr1[n * 4 + j] * x1[j].y;
                    }
                    *(float2*)(out + ((size_t)r1 * 4 + n) * CDIM + c0) = make_float2(ox, oy);
                }
            }
        }
    }
}

// ---------------- launch ----------------
extern "C" void kernel_launch(void* const* d_in, const int* in_sizes, int n_in,
                              void* d_out, int out_size) {
    const float* x     = (const float*)d_in[0];
    const float* phi   = (const float*)d_in[1];
    const float* b     = (const float*)d_in[2];
    const float* apre  = (const float*)d_in[3];
    const float* apost = (const float*)d_in[4];
    const float* ares  = (const float*)d_in[5];
    const float* W1    = (const float*)d_in[6];
    const float* b1    = (const float*)d_in[7];
    const float* W2    = (const float*)d_in[8];
    const float* b2    = (const float*)d_in[9];
    float* out = (float*)d_out;

    const int dyn_smem = HP_STAGES * HP_STG_BYTES;   // 96 KB
    cudaFuncSetAttribute(gemm_hp<CDIM, 1>,  cudaFuncAttributeMaxDynamicSharedMemorySize, dyn_smem);
    cudaFuncSetAttribute(gemm_hp<NCDIM, 2>, cudaFuncAttributeMaxDynamicSharedMemorySize, dyn_smem);

    sumsq_convert_kernel<<<SSBLKS + WCBLKS, 256>>>(x, phi, W1, W2);
    mix_routing_kernel<<<MIXBLKS, 128>>>(b, apre, apost, ares);
    xin_kernel<<<TOK * 384 / 256, 256>>>();
    gemm_hp<CDIM, 1><<<dim3(DFFDIM / 128, TOK / 128), HP_THREADS, dyn_smem>>>(b1, nullptr);
    gemm_hp<NCDIM, 2><<<dim3(CDIM / 128, TOK / 128), HP_THREADS, dyn_smem>>>(b2, out);
}